// round 1
// baseline (speedup 1.0000x reference)
#include <cuda_runtime.h>

// Problem constants (fixed shapes per reference)
#define NB 8      // batch
#define IC 16     // input channels
#define OC 32     // output channels
#define H  128
#define W  128
#define TH 2      // output rows per block

typedef unsigned long long ull;

// Coefficient table: [j][i][k(padded to 4)] = (cos(theta[i*j,k]), -sin(theta[i*j,k]))
// 16*32*4 float2 = 16 KB.
__device__ float2 g_coef[IC * OC * 4];

__global__ void coef_kernel(const float* __restrict__ theta) {
    int t = blockIdx.x * blockDim.x + threadIdx.x;
    if (t >= IC * OC * 4) return;
    int j = t >> 7;            // / (32*4)
    int i = (t >> 2) & 31;
    int k = t & 3;
    float2 v = make_float2(0.f, 0.f);
    if (k < 3) {
        float th = theta[(i * j) * 3 + k];
        float s, c;
        sincosf(th, &s, &c);   // accurate version for the tiny table
        v = make_float2(c, -s);
    }
    g_coef[t] = v;
}

// Packed dual-FMA: d.lo += a.lo*b.lo ; d.hi += a.hi*b.hi  (sm_100+ f32x2)
__device__ __forceinline__ void ffma2(ull& d, ull a, ull b) {
    asm("fma.rn.f32x2 %0, %1, %2, %0;" : "+l"(d) : "l"(a), "l"(b));
}

__global__ __launch_bounds__(256, 2)
void qconv_kernel(const float* __restrict__ x, float* __restrict__ out) {
    __shared__ float2 sCoef[IC * OC * 4];     // 16 KB
    __shared__ float  sX[(TH + 2) * 130];     // padded x tile: 4 rows x 130 cols
    __shared__ float2 sCS[(TH + 2) * W];      // (cos S, sin S): 4 rows x 128 cols

    const int tid = threadIdx.x;
    const int n   = blockIdx.y;
    const int h0  = blockIdx.x * TH;

    // Stage coefficient table into smem (broadcast-read later)
    {
        const float4* src = reinterpret_cast<const float4*>(g_coef);
        float4* dst = reinterpret_cast<float4*>(sCoef);
        for (int idx = tid; idx < IC * OC * 2; idx += 256)  // 1024 float4
            dst[idx] = src[idx];
    }

    const int row = tid >> 7;     // 0..TH-1
    const int w   = tid & 127;

    ull acc[OC];
    #pragma unroll
    for (int i = 0; i < OC; ++i) acc[i] = 0ull;

    const ull* csp = reinterpret_cast<const ull*>(sCS);

    #pragma unroll 1
    for (int j = 0; j < IC; ++j) {
        // Phase A1: stage padded x rows [h0-1, h0+TH] x cols [-1,128] into smem
        const float* xj = x + ((size_t)(n * IC + j) * H) * W;
        for (int idx = tid; idx < (TH + 2) * 130; idx += 256) {
            int rr = idx / 130, cc = idx - rr * 130;
            int gr = h0 - 1 + rr;
            int gc = cc - 1;
            float v = 0.f;
            if ((unsigned)gr < (unsigned)H && (unsigned)gc < (unsigned)W)
                v = xj[gr * W + gc];
            sX[idx] = v;
        }
        __syncthreads();

        // Phase A2: horizontal 3-window sums + sincos -> packed (cos,sin)
        for (int idx = tid; idx < (TH + 2) * W; idx += 256) {
            int r = idx >> 7, ww = idx & 127;
            float S = sX[r * 130 + ww] + sX[r * 130 + ww + 1] + sX[r * 130 + ww + 2];
            float s, c;
            __sincosf(S, &s, &c);
            sCS[idx] = make_float2(c, s);
        }
        __syncthreads();

        // Phase B: contraction. d_k = (cos S, sin S) at rows row+k, column w.
        ull d0 = csp[(row + 0) * W + w];
        ull d1 = csp[(row + 1) * W + w];
        ull d2 = csp[(row + 2) * W + w];

        const ulonglong2* cf =
            reinterpret_cast<const ulonglong2*>(sCoef) + (size_t)j * OC * 2;
        const ull* cfu = reinterpret_cast<const ull*>(cf);

        #pragma unroll
        for (int i = 0; i < OC; ++i) {
            ulonglong2 q01 = cf[i * 2];          // k=0,1 coefficient pairs (LDS.128)
            ull        q2  = cfu[i * 4 + 2];     // k=2 pair                (LDS.64)
            ffma2(acc[i], d0, q01.x);
            ffma2(acc[i], d1, q01.y);
            ffma2(acc[i], d2, q2);
        }
        // No trailing sync needed: next iteration's Phase-A1 writes only sX
        // (not read by Phase B), and the sync after A1 orders everything
        // before sCS is overwritten in A2.
    }

    // Epilogue: out = (acc.lo + acc.hi) / 3
    const int h = h0 + row;
    float* op = out + ((size_t)n * OC * H + h) * W + w;
    #pragma unroll
    for (int i = 0; i < OC; ++i) {
        float lo = __uint_as_float((unsigned)(acc[i] & 0xffffffffu));
        float hi = __uint_as_float((unsigned)(acc[i] >> 32));
        op[(size_t)i * H * W] = (lo + hi) * (1.0f / 3.0f);
    }
}

extern "C" void kernel_launch(void* const* d_in, const int* in_sizes, int n_in,
                              void* d_out, int out_size) {
    const float* x     = (const float*)d_in[0];   // (8,16,128,128) f32
    const float* theta = (const float*)d_in[1];   // (1536,3) f32
    float* out = (float*)d_out;                   // (8,32,128,128) f32

    coef_kernel<<<(IC * OC * 4 + 255) / 256, 256>>>(theta);

    dim3 grid(H / TH, NB);   // 64 x 8 = 512 blocks
    qconv_kernel<<<grid, 256>>>(x, out);
}

// round 2
// speedup vs baseline: 1.1840x; 1.1840x over previous
#include <cuda_runtime.h>

// Fixed problem shape
#define NB 8      // batch
#define IC 16     // input channels
#define OC 32     // output channels
#define H  128
#define W  128
#define TH 2      // output rows per block

typedef unsigned long long ull;

// Coefficient table: [j][i][k(padded to 4)] = (cos(theta[i*j,k]), -sin(theta[i*j,k]))
// 16*32*4 float2 = 16 KB
__device__ float2 g_coef[IC * OC * 4];

__global__ void coef_kernel(const float* __restrict__ theta) {
    int t = blockIdx.x * blockDim.x + threadIdx.x;
    if (t >= IC * OC * 4) return;
    int j = t >> 7;            // / (32*4)
    int i = (t >> 2) & 31;
    int k = t & 3;
    float2 v = make_float2(0.f, 0.f);
    if (k < 3) {
        float th = theta[(i * j) * 3 + k];
        float s, c;
        sincosf(th, &s, &c);   // accurate version for the tiny table
        v = make_float2(c, -s);
    }
    g_coef[t] = v;
}

// Packed dual-FMA: d.lo += a.lo*b.lo ; d.hi += a.hi*b.hi  (sm_100+ f32x2)
__device__ __forceinline__ void ffma2(ull& d, ull a, ull b) {
    asm("fma.rn.f32x2 %0, %1, %2, %0;" : "+l"(d) : "l"(a), "l"(b));
}

__device__ __forceinline__ ull pack2(float lo, float hi) {
    return (ull)__float_as_uint(lo) | ((ull)__float_as_uint(hi) << 32);
}

__global__ __launch_bounds__(256, 2)
void qconv_kernel(const float* __restrict__ x, float* __restrict__ out) {
    __shared__ float2 sCoef[IC * OC * 4];        // 16 KB: [j][i][k4]
    __shared__ float  sX[(TH + 2) * 130];        // padded x tile: 4 rows x 130
    __shared__ ull    sCS[(TH + 2) * W];         // packed (cos S, sin S): 4 rows x 128

    const int tid  = threadIdx.x;
    const int lane = tid & 31;
    const int wid  = tid >> 5;            // warp 0..7 -> i-group = 4*wid
    const int n    = blockIdx.y;
    const int h0   = blockIdx.x * TH;

    // Stage coefficient table (4 float4 per thread)
    {
        const float4* src = reinterpret_cast<const float4*>(g_coef);
        float4* dst = reinterpret_cast<float4*>(sCoef);
        #pragma unroll
        for (int r = 0; r < 4; ++r)
            dst[tid + 256 * r] = src[tid + 256 * r];
    }

    // acc[c][i][r]: c = w-column group (w = lane + 32c), i = channel in warp's
    // group, r = output row (h0 + r). Packed: lo = cos-branch, hi = sin-branch.
    ull acc[4][4][2];
    #pragma unroll
    for (int c = 0; c < 4; ++c)
        #pragma unroll
        for (int i = 0; i < 4; ++i) {
            acc[c][i][0] = 0ull;
            acc[c][i][1] = 0ull;
        }

    #pragma unroll 1
    for (int j = 0; j < IC; ++j) {
        // Phase A1: stage padded x rows [h0-1, h0+2] x cols [-1,128]
        const float* xj = x + ((size_t)(n * IC + j) * H) * W;
        for (int idx = tid; idx < (TH + 2) * 130; idx += 256) {
            int rr = idx / 130, cc = idx - rr * 130;
            int gr = h0 - 1 + rr;
            int gc = cc - 1;
            float v = 0.f;
            if ((unsigned)gr < (unsigned)H && (unsigned)gc < (unsigned)W)
                v = xj[gr * W + gc];
            sX[idx] = v;
        }
        __syncthreads();

        // Phase A2: horizontal 3-window sums + sincos -> packed (cos, sin)
        for (int idx = tid; idx < (TH + 2) * W; idx += 256) {
            int r = idx >> 7, ww = idx & 127;
            float S = sX[r * 130 + ww] + sX[r * 130 + ww + 1] + sX[r * 130 + ww + 2];
            float s, c;
            __sincosf(S, &s, &c);
            sCS[idx] = pack2(c, s);
        }
        __syncthreads();

        // Phase B: warp-broadcast coefficient loads, hoisted into registers.
        // Coef layout: sCoef[(j*OC + i)*4 + k]; all lanes read same addr.
        const ull* cf = reinterpret_cast<const ull*>(sCoef + ((size_t)j * OC + wid * 4) * 4);
        ull c0[4], c1[4], c2[4];
        #pragma unroll
        for (int i = 0; i < 4; ++i) {
            c0[i] = cf[i * 4 + 0];
            c1[i] = cf[i * 4 + 1];
            c2[i] = cf[i * 4 + 2];
        }

        #pragma unroll
        for (int c = 0; c < 4; ++c) {
            const int w = lane + 32 * c;
            ull d0 = sCS[0 * W + w];
            ull d1 = sCS[1 * W + w];
            ull d2 = sCS[2 * W + w];
            ull d3 = sCS[3 * W + w];
            #pragma unroll
            for (int i = 0; i < 4; ++i) {
                ffma2(acc[c][i][0], d0, c0[i]);
                ffma2(acc[c][i][0], d1, c1[i]);
                ffma2(acc[c][i][0], d2, c2[i]);
                ffma2(acc[c][i][1], d1, c0[i]);
                ffma2(acc[c][i][1], d2, c1[i]);
                ffma2(acc[c][i][1], d3, c2[i]);
            }
        }
        // Next iteration's A1 writes only sX (not read here); the sync after
        // A1 orders all Phase-B reads before A2 overwrites sCS.
    }

    // Epilogue: out[n, 4*wid+i, h0+r, lane+32c] = (acc.lo + acc.hi) / 3
    #pragma unroll
    for (int i = 0; i < 4; ++i) {
        const int ig = wid * 4 + i;
        float* op = out + ((size_t)(n * OC + ig) * H + h0) * W;
        #pragma unroll
        for (int r = 0; r < 2; ++r)
            #pragma unroll
            for (int c = 0; c < 4; ++c) {
                ull a = acc[c][i][r];
                float lo = __uint_as_float((unsigned)(a & 0xffffffffu));
                float hi = __uint_as_float((unsigned)(a >> 32));
                op[r * W + lane + 32 * c] = (lo + hi) * (1.0f / 3.0f);
            }
    }
}

extern "C" void kernel_launch(void* const* d_in, const int* in_sizes, int n_in,
                              void* d_out, int out_size) {
    const float* x     = (const float*)d_in[0];   // (8,16,128,128) f32
    const float* theta = (const float*)d_in[1];   // (1536,3) f32
    float* out = (float*)d_out;                   // (8,32,128,128) f32

    coef_kernel<<<(IC * OC * 4 + 255) / 256, 256>>>(theta);

    dim3 grid(H / TH, NB);   // 64 x 8 = 512 blocks
    qconv_kernel<<<grid, 256>>>(x, out);
}

// round 3
// speedup vs baseline: 1.2833x; 1.0839x over previous
#include <cuda_runtime.h>

// Fixed problem shape
#define NB 8      // batch
#define IC 16     // input channels
#define OC 32     // output channels
#define H  128
#define W  128
#define TH 2      // output rows per block

typedef unsigned long long ull;

// Coefficient table: [j][i][k(padded to 4)] = (cos(theta[i*j,k]), -sin(theta[i*j,k]))
__device__ float2 g_coef[IC * OC * 4];   // 16 KB

__global__ void coef_kernel(const float* __restrict__ theta) {
    int t = blockIdx.x * blockDim.x + threadIdx.x;
    if (t >= IC * OC * 4) return;
    int j = t >> 7;
    int i = (t >> 2) & 31;
    int k = t & 3;
    float2 v = make_float2(0.f, 0.f);
    if (k < 3) {
        float th = theta[(i * j) * 3 + k];
        float s, c;
        sincosf(th, &s, &c);
        v = make_float2(c, -s);
    }
    g_coef[t] = v;
}

// Packed dual-FMA: d.lo += a.lo*b.lo ; d.hi += a.hi*b.hi
__device__ __forceinline__ void ffma2(ull& d, ull a, ull b) {
    asm("fma.rn.f32x2 %0, %1, %2, %0;" : "+l"(d) : "l"(a), "l"(b));
}

__device__ __forceinline__ ull pack2(float lo, float hi) {
    return (ull)__float_as_uint(lo) | ((ull)__float_as_uint(hi) << 32);
}

__global__ __launch_bounds__(256, 2)
void qconv_kernel(const float* __restrict__ x, float* __restrict__ out) {
    // All 16 channels' (cos S, sin S) for 4 CS-rows x 128 cols: 64 KB
    __shared__ __align__(16) ull sCS[IC * 4 * W];
    __shared__ float2 sCoef[IC * OC * 4];          // 16 KB

    const int tid  = threadIdx.x;
    const int lane = tid & 31;
    const int wid  = tid >> 5;            // warp 0..7 -> i-group = 4*wid
    const int n    = blockIdx.y;
    const int h0   = blockIdx.x * TH;

    // ---- Stage coefficient table (1024 float4, 4 per thread) ----
    {
        const float4* src = reinterpret_cast<const float4*>(g_coef);
        float4* dst = reinterpret_cast<float4*>(sCoef);
        #pragma unroll
        for (int r = 0; r < 4; ++r)
            dst[tid + 256 * r] = src[tid + 256 * r];
    }

    // ---- Stage CS tile: all 16 j, CS rows h0..h0+3 (padded-x rows h0-1..h0+2) ----
    // CS row r (r=0..3) = 3-window sum of padded x row (h0-1+r); zero rows give
    // S=0 -> (cos,sin)=(1,0), which the contraction needs (do NOT skip them).
    #pragma unroll 1
    for (int it = 0; it < 32; ++it) {
        int idx = it * 256 + tid;          // idx&31 == lane -> warp = 32 consecutive w
        int w = idx & 127;
        int r = (idx >> 7) & 3;
        int j = idx >> 9;
        int gr = h0 - 1 + r;               // x row
        bool rowok = (unsigned)gr < (unsigned)H;
        const float* xr = x + ((size_t)((n * IC + j) * H) + gr) * W;
        float v = rowok ? xr[w] : 0.f;
        float vm = __shfl_up_sync(0xffffffffu, v, 1);
        if (lane == 0)  vm = (rowok && w > 0)   ? xr[w - 1] : 0.f;
        float vp = __shfl_down_sync(0xffffffffu, v, 1);
        if (lane == 31) vp = (rowok && w < 127) ? xr[w + 1] : 0.f;
        float S = vm + v + vp;
        float s, c;
        __sincosf(S, &s, &c);
        sCS[idx] = pack2(c, s);
    }
    __syncthreads();   // the ONLY barrier

    // ---- Contraction: warp owns i-group 4*wid; thread owns columns
    //      {2*lane, 2*lane+1, 64+2*lane, 64+2*lane+1} and rows h0, h0+1. ----
    // acc[cp][col01][i][r], packed lo=cos-branch, hi=sin-branch.
    ull acc[2][2][4][2];
    #pragma unroll
    for (int cp = 0; cp < 2; ++cp)
        #pragma unroll
        for (int q = 0; q < 2; ++q)
            #pragma unroll
            for (int i = 0; i < 4; ++i) {
                acc[cp][q][i][0] = 0ull;
                acc[cp][q][i][1] = 0ull;
            }

    #pragma unroll 1
    for (int j = 0; j < IC; ++j) {
        // Hoist this j's 12 coefficient pairs (warp-broadcast LDS)
        const ull* cf = reinterpret_cast<const ull*>(
            sCoef + ((size_t)j * OC + wid * 4) * 4);
        ull c0[4], c1[4], c2[4];
        #pragma unroll
        for (int i = 0; i < 4; ++i) {
            c0[i] = cf[i * 4 + 0];
            c1[i] = cf[i * 4 + 1];
            c2[i] = cf[i * 4 + 2];
        }

        const ull* base = sCS + j * 4 * W;
        #pragma unroll
        for (int cp = 0; cp < 2; ++cp) {
            const int w0 = cp * 64 + 2 * lane;
            // 4 CS rows, two adjacent columns each: LDS.128
            ulonglong2 e0 = *reinterpret_cast<const ulonglong2*>(base + 0 * W + w0);
            ulonglong2 e1 = *reinterpret_cast<const ulonglong2*>(base + 1 * W + w0);
            ulonglong2 e2 = *reinterpret_cast<const ulonglong2*>(base + 2 * W + w0);
            ulonglong2 e3 = *reinterpret_cast<const ulonglong2*>(base + 3 * W + w0);
            #pragma unroll
            for (int i = 0; i < 4; ++i) {
                // column .x (w0), output rows r=0,1
                ffma2(acc[cp][0][i][0], e0.x, c0[i]);
                ffma2(acc[cp][0][i][0], e1.x, c1[i]);
                ffma2(acc[cp][0][i][0], e2.x, c2[i]);
                ffma2(acc[cp][0][i][1], e1.x, c0[i]);
                ffma2(acc[cp][0][i][1], e2.x, c1[i]);
                ffma2(acc[cp][0][i][1], e3.x, c2[i]);
                // column .y (w0+1)
                ffma2(acc[cp][1][i][0], e0.y, c0[i]);
                ffma2(acc[cp][1][i][0], e1.y, c1[i]);
                ffma2(acc[cp][1][i][0], e2.y, c2[i]);
                ffma2(acc[cp][1][i][1], e1.y, c0[i]);
                ffma2(acc[cp][1][i][1], e2.y, c1[i]);
                ffma2(acc[cp][1][i][1], e3.y, c2[i]);
            }
        }
    }

    // ---- Epilogue: out = (lo + hi) / 3, STG.64 over adjacent column pairs ----
    #pragma unroll
    for (int i = 0; i < 4; ++i) {
        const int ig = wid * 4 + i;
        float* op = out + ((size_t)(n * OC + ig) * H + h0) * W;
        #pragma unroll
        for (int r = 0; r < 2; ++r)
            #pragma unroll
            for (int cp = 0; cp < 2; ++cp) {
                const int w0 = cp * 64 + 2 * lane;
                ull ax = acc[cp][0][i][r];
                ull ay = acc[cp][1][i][r];
                float2 o;
                o.x = (__uint_as_float((unsigned)(ax & 0xffffffffu)) +
                       __uint_as_float((unsigned)(ax >> 32))) * (1.0f / 3.0f);
                o.y = (__uint_as_float((unsigned)(ay & 0xffffffffu)) +
                       __uint_as_float((unsigned)(ay >> 32))) * (1.0f / 3.0f);
                *reinterpret_cast<float2*>(op + r * W + w0) = o;
            }
    }
}

extern "C" void kernel_launch(void* const* d_in, const int* in_sizes, int n_in,
                              void* d_out, int out_size) {
    const float* x     = (const float*)d_in[0];   // (8,16,128,128) f32
    const float* theta = (const float*)d_in[1];   // (1536,3) f32
    float* out = (float*)d_out;                   // (8,32,128,128) f32

    coef_kernel<<<(IC * OC * 4 + 255) / 256, 256>>>(theta);

    dim3 grid(H / TH, NB);   // 64 x 8 = 512 blocks
    qconv_kernel<<<grid, 256>>>(x, out);
}

// round 4
// speedup vs baseline: 1.4944x; 1.1645x over previous
#include <cuda_runtime.h>

// Fixed problem shape
#define NB 8      // batch
#define IC 16     // input channels
#define OC 32     // output channels
#define H  128
#define W  128
#define TH 2      // output rows per block

typedef unsigned long long ull;

// Coefficient table: [j][i][k(padded to 4)] = (cos(theta[i*j,k]), -sin(theta[i*j,k]))
__device__ float2 g_coef[IC * OC * 4];   // 16 KB

__global__ void coef_kernel(const float* __restrict__ theta) {
    int t = blockIdx.x * blockDim.x + threadIdx.x;
    if (t >= IC * OC * 4) return;
    int j = t >> 7;
    int i = (t >> 2) & 31;
    int k = t & 3;
    float2 v = make_float2(0.f, 0.f);
    if (k < 3) {
        float th = theta[(i * j) * 3 + k];
        float s, c;
        sincosf(th, &s, &c);
        v = make_float2(c, -s);
    }
    g_coef[t] = v;
}

// Packed dual-FMA: d.lo += a.lo*b.lo ; d.hi += a.hi*b.hi
__device__ __forceinline__ void ffma2(ull& d, ull a, ull b) {
    asm("fma.rn.f32x2 %0, %1, %2, %0;" : "+l"(d) : "l"(a), "l"(b));
}

__device__ __forceinline__ ull pack2(float lo, float hi) {
    return (ull)__float_as_uint(lo) | ((ull)__float_as_uint(hi) << 32);
}

__global__ __launch_bounds__(256, 2)
void qconv_kernel(const float* __restrict__ x, float* __restrict__ out) {
    // All 16 channels' packed (cos S, sin S), 4 CS-rows x 128 cols: 64 KB
    __shared__ __align__(16) ull sCS[IC * 4 * W];
    __shared__ float2 sCoef[IC * OC * 4];          // 16 KB

    const int tid  = threadIdx.x;
    const int lane = tid & 31;
    const int wid  = tid >> 5;            // warp 0..7 -> i-group = 4*wid
    const int n    = blockIdx.y;
    const int h0   = blockIdx.x * TH;

    // ---- Stage coefficient table (1024 float4, 4 per thread) ----
    {
        const float4* src = reinterpret_cast<const float4*>(g_coef);
        float4* dst = reinterpret_cast<float4*>(sCoef);
        #pragma unroll
        for (int r = 0; r < 4; ++r)
            dst[tid + 256 * r] = src[tid + 256 * r];
    }

    // ---- Stage CS tile: all 16 j, CS rows h0..h0+3 (x rows h0-1..h0+2) ----
    // Thread owns fixed column w; iteration it covers (j, r) = rj = 2*it + half.
    // Pass 1: batch ALL main loads into registers (MLP ~32).
    const int w    = tid & 127;
    const int half = tid >> 7;
    const float* xbase = x + (size_t)n * IC * H * W;

    float v[32];
    #pragma unroll
    for (int it = 0; it < 32; ++it) {
        int rj = it * 2 + half;
        int r = rj & 3, j = rj >> 2;
        int gr = h0 - 1 + r;
        bool rowok = (unsigned)gr < (unsigned)H;
        float t0 = 0.f;
        if (rowok) t0 = xbase[((size_t)j * H + gr) * W + w];
        v[it] = t0;
    }

    // Pass 2: window sum via shfl (edge fixups are L1 hits on the lines
    // pass 1 just fetched), sincos, pack, STS.
    #pragma unroll
    for (int it = 0; it < 32; ++it) {
        int rj = it * 2 + half;
        int r = rj & 3, j = rj >> 2;
        int gr = h0 - 1 + r;
        bool rowok = (unsigned)gr < (unsigned)H;
        const float* xr = xbase + ((size_t)j * H + gr) * W;
        float vm = __shfl_up_sync(0xffffffffu, v[it], 1);
        if (lane == 0)  vm = (rowok && w > 0)   ? xr[w - 1] : 0.f;
        float vp = __shfl_down_sync(0xffffffffu, v[it], 1);
        if (lane == 31) vp = (rowok && w < 127) ? xr[w + 1] : 0.f;
        float S = vm + v[it] + vp;
        float s, c;
        __sincosf(S, &s, &c);
        sCS[rj * W + w] = pack2(c, s);
    }
    __syncthreads();   // the ONLY barrier

    // ---- Contraction: warp owns i-group 4*wid; thread owns columns
    //      {2*lane, 2*lane+1, 64+2*lane, 64+2*lane+1}, rows h0, h0+1 ----
    ull acc[2][2][4][2];
    #pragma unroll
    for (int cp = 0; cp < 2; ++cp)
        #pragma unroll
        for (int q = 0; q < 2; ++q)
            #pragma unroll
            for (int i = 0; i < 4; ++i) {
                acc[cp][q][i][0] = 0ull;
                acc[cp][q][i][1] = 0ull;
            }

    #pragma unroll 1
    for (int j = 0; j < IC; ++j) {
        // Hoist this j's 12 coefficient pairs (warp-broadcast LDS)
        const ull* cf = reinterpret_cast<const ull*>(
            sCoef + ((size_t)j * OC + wid * 4) * 4);
        ull c0[4], c1[4], c2[4];
        #pragma unroll
        for (int i = 0; i < 4; ++i) {
            c0[i] = cf[i * 4 + 0];
            c1[i] = cf[i * 4 + 1];
            c2[i] = cf[i * 4 + 2];
        }

        const ull* base = sCS + j * 4 * W;
        #pragma unroll
        for (int cp = 0; cp < 2; ++cp) {
            const int w0 = cp * 64 + 2 * lane;
            ulonglong2 e0 = *reinterpret_cast<const ulonglong2*>(base + 0 * W + w0);
            ulonglong2 e1 = *reinterpret_cast<const ulonglong2*>(base + 1 * W + w0);
            ulonglong2 e2 = *reinterpret_cast<const ulonglong2*>(base + 2 * W + w0);
            ulonglong2 e3 = *reinterpret_cast<const ulonglong2*>(base + 3 * W + w0);
            #pragma unroll
            for (int i = 0; i < 4; ++i) {
                ffma2(acc[cp][0][i][0], e0.x, c0[i]);
                ffma2(acc[cp][0][i][0], e1.x, c1[i]);
                ffma2(acc[cp][0][i][0], e2.x, c2[i]);
                ffma2(acc[cp][0][i][1], e1.x, c0[i]);
                ffma2(acc[cp][0][i][1], e2.x, c1[i]);
                ffma2(acc[cp][0][i][1], e3.x, c2[i]);
                ffma2(acc[cp][1][i][0], e0.y, c0[i]);
                ffma2(acc[cp][1][i][0], e1.y, c1[i]);
                ffma2(acc[cp][1][i][0], e2.y, c2[i]);
                ffma2(acc[cp][1][i][1], e1.y, c0[i]);
                ffma2(acc[cp][1][i][1], e2.y, c1[i]);
                ffma2(acc[cp][1][i][1], e3.y, c2[i]);
            }
        }
    }

    // ---- Epilogue: out = (lo + hi) / 3, STG.64 ----
    #pragma unroll
    for (int i = 0; i < 4; ++i) {
        const int ig = wid * 4 + i;
        float* op = out + ((size_t)(n * OC + ig) * H + h0) * W;
        #pragma unroll
        for (int r = 0; r < 2; ++r)
            #pragma unroll
            for (int cp = 0; cp < 2; ++cp) {
                const int w0 = cp * 64 + 2 * lane;
                ull ax = acc[cp][0][i][r];
                ull ay = acc[cp][1][i][r];
                float2 o;
                o.x = (__uint_as_float((unsigned)(ax & 0xffffffffu)) +
                       __uint_as_float((unsigned)(ax >> 32))) * (1.0f / 3.0f);
                o.y = (__uint_as_float((unsigned)(ay & 0xffffffffu)) +
                       __uint_as_float((unsigned)(ay >> 32))) * (1.0f / 3.0f);
                *reinterpret_cast<float2*>(op + r * W + w0) = o;
            }
    }
}

extern "C" void kernel_launch(void* const* d_in, const int* in_sizes, int n_in,
                              void* d_out, int out_size) {
    const float* x     = (const float*)d_in[0];   // (8,16,128,128) f32
    const float* theta = (const float*)d_in[1];   // (1536,3) f32
    float* out = (float*)d_out;                   // (8,32,128,128) f32

    coef_kernel<<<(IC * OC * 4 + 255) / 256, 256>>>(theta);

    dim3 grid(H / TH, NB);   // 64 x 8 = 512 blocks
    qconv_kernel<<<grid, 256>>>(x, out);
}